// round 1
// baseline (speedup 1.0000x reference)
#include <cuda_runtime.h>
#include <math.h>

#define BATCH   16384
#define EMB     128
#define NCAT    26
#define NFEAT   27
#define NPAIR   351
#define TOPIN   480

// ---------------- scratch (device globals; allocation-free) ----------------
__device__ float g_h1[BATCH * 512];
__device__ float g_h2[BATCH * 256];
__device__ float g_bot[BATCH * 128];
__device__ float g_x [BATCH * TOPIN];
__device__ float g_t1[BATCH * 1024];
__device__ float g_t2[BATCH * 1024];
__device__ float g_t3[BATCH * 512];
__device__ float g_t4[BATCH * 256];

// ---------------- bottom layer 1: [B,13] -> [B,512], relu ------------------
__global__ __launch_bounds__(256) void bottom1_kernel(
    const float* __restrict__ X, const float* __restrict__ W,
    const float* __restrict__ bias)
{
    __shared__ float ws[512 * 13];
    __shared__ float bs[512];
    __shared__ float xs[32 * 13];
    const int tid  = threadIdx.x;
    const int row0 = blockIdx.x * 32;

    for (int i = tid; i < 512 * 13; i += 256) ws[i] = W[i];
    for (int i = tid; i < 512;      i += 256) bs[i] = bias[i];
    for (int i = tid; i < 32 * 13;  i += 256) xs[i] = X[row0 * 13 + i];
    __syncthreads();

    for (int o = tid; o < 32 * 512; o += 256) {
        const int col = o & 511;
        const int row = o >> 9;
        float acc = bs[col];
        #pragma unroll
        for (int k = 0; k < 13; k++)
            acc = fmaf(xs[row * 13 + k], ws[col * 13 + k], acc);
        g_h1[(row0 + row) * 512 + col] = fmaxf(acc, 0.0f);
    }
}

// ---------------- generic SGEMM: C[B,N] = act(A[B,K] @ W[N,K]^T + b) -------
// Requires K % 16 == 0, N % 128 == 0, B % 128 == 0.
// grid = (N/128, B/128), block = 256 threads, each thread computes 8x8.
__global__ __launch_bounds__(256) void gemm_bias_relu(
    const float* __restrict__ A, const float* __restrict__ W,
    const float* __restrict__ bias, float* __restrict__ C,
    int K, int N, int relu)
{
    __shared__ float As[16][132];
    __shared__ float Ws[16][132];

    const int tid  = threadIdx.x;
    const int tx   = tid & 15;       // 0..15 -> col octet
    const int ty   = tid >> 4;       // 0..15 -> row octet
    const int row0 = blockIdx.y * 128;
    const int col0 = blockIdx.x * 128;

    const float* Ablk = A + (long)row0 * K;
    const float* Wblk = W + (long)col0 * K;

    float acc[8][8];
    #pragma unroll
    for (int i = 0; i < 8; i++)
        #pragma unroll
        for (int j = 0; j < 8; j++) acc[i][j] = 0.0f;

    for (int kt = 0; kt < K; kt += 16) {
        // cooperative load: 128 rows x 16 k each for A and W (512 float4 each)
        #pragma unroll
        for (int i = 0; i < 2; i++) {
            const int li  = tid + i * 256;
            const int row = li >> 2;
            const int kq  = (li & 3) * 4;
            float4 va = *(const float4*)(Ablk + (long)row * K + kt + kq);
            As[kq + 0][row] = va.x; As[kq + 1][row] = va.y;
            As[kq + 2][row] = va.z; As[kq + 3][row] = va.w;
            float4 vw = *(const float4*)(Wblk + (long)row * K + kt + kq);
            Ws[kq + 0][row] = vw.x; Ws[kq + 1][row] = vw.y;
            Ws[kq + 2][row] = vw.z; Ws[kq + 3][row] = vw.w;
        }
        __syncthreads();

        #pragma unroll
        for (int k = 0; k < 16; k++) {
            float4 a0 = *(const float4*)&As[k][ty * 8];
            float4 a1 = *(const float4*)&As[k][ty * 8 + 4];
            float4 w0 = *(const float4*)&Ws[k][tx * 8];
            float4 w1 = *(const float4*)&Ws[k][tx * 8 + 4];
            float a[8] = {a0.x, a0.y, a0.z, a0.w, a1.x, a1.y, a1.z, a1.w};
            float w[8] = {w0.x, w0.y, w0.z, w0.w, w1.x, w1.y, w1.z, w1.w};
            #pragma unroll
            for (int i = 0; i < 8; i++)
                #pragma unroll
                for (int j = 0; j < 8; j++)
                    acc[i][j] = fmaf(a[i], w[j], acc[i][j]);
        }
        __syncthreads();
    }

    // epilogue: bias + optional relu, vectorized stores
    float4 b0 = *(const float4*)(bias + col0 + tx * 8);
    float4 b1 = *(const float4*)(bias + col0 + tx * 8 + 4);
    const float bv[8] = {b0.x, b0.y, b0.z, b0.w, b1.x, b1.y, b1.z, b1.w};

    #pragma unroll
    for (int i = 0; i < 8; i++) {
        float v[8];
        #pragma unroll
        for (int j = 0; j < 8; j++) {
            float t = acc[i][j] + bv[j];
            v[j] = relu ? fmaxf(t, 0.0f) : t;
        }
        float* crow = C + (long)(row0 + ty * 8 + i) * N + col0 + tx * 8;
        *(float4*)(crow)     = make_float4(v[0], v[1], v[2], v[3]);
        *(float4*)(crow + 4) = make_float4(v[4], v[5], v[6], v[7]);
    }
}

// ---------------- gather + pairwise interactions ---------------------------
// one block (128 threads) per sample; builds g_x row = [bottom | 351 dots | 0]
__global__ __launch_bounds__(128) void interact_kernel(
    const int* __restrict__ cat, const float* __restrict__ emb)
{
    __shared__ float sm[NFEAT * 129];
    const int b   = blockIdx.x;
    const int tid = threadIdx.x;   // 0..127 = embedding dim

    // feature 0 = bottom MLP output
    sm[tid] = g_bot[b * EMB + tid];
    #pragma unroll 1
    for (int t = 0; t < NCAT; t++) {
        const int idx = cat[t * BATCH + b];
        sm[(t + 1) * 129 + tid] = emb[((long)t * 100000 + idx) * EMB + tid];
    }
    __syncthreads();

    float* xrow = g_x + (long)b * TOPIN;
    xrow[tid] = sm[tid];               // copy bottom into x[:,0:128]

    for (int p = tid; p < NPAIR; p += 128) {
        int r = (int)((1.0f + sqrtf(8.0f * (float)p + 1.0f)) * 0.5f);
        if (r * (r - 1) / 2 > p) r--;
        if ((r + 1) * r / 2 <= p) r++;
        const int c = p - r * (r - 1) / 2;
        const float* fr = sm + r * 129;
        const float* fc = sm + c * 129;
        float acc = 0.0f;
        #pragma unroll
        for (int d = 0; d < EMB; d++) acc = fmaf(fr[d], fc[d], acc);
        xrow[EMB + p] = acc;
    }
    if (tid == 0) xrow[TOPIN - 1] = 0.0f;   // zero pad column
}

// ---------------- final layer: dot(256) + sigmoid ---------------------------
__global__ __launch_bounds__(256) void final_kernel(
    const float* __restrict__ w5, const float* __restrict__ b5,
    float* __restrict__ out)
{
    const int warp = threadIdx.x >> 5;
    const int lane = threadIdx.x & 31;
    const int b = blockIdx.x * 8 + warp;
    const float* row = g_t4 + (long)b * 256;
    float s = 0.0f;
    #pragma unroll
    for (int j = lane; j < 256; j += 32) s = fmaf(row[j], w5[j], s);
    #pragma unroll
    for (int o = 16; o; o >>= 1) s += __shfl_xor_sync(0xffffffffu, s, o);
    if (lane == 0) out[b] = 1.0f / (1.0f + expf(-(s + b5[0])));
}

// ---------------- launcher --------------------------------------------------
static float* sym_addr(const void* symbol)
{
    void* p = nullptr;
    cudaGetSymbolAddress(&p, symbol);
    return (float*)p;
}

extern "C" void kernel_launch(void* const* d_in, const int* in_sizes, int n_in,
                              void* d_out, int out_size)
{
    const float* Xnum = (const float*)d_in[0];
    const int*   cat  = (const int*)  d_in[1];
    const float* emb  = (const float*)d_in[2];
    const float* bw1  = (const float*)d_in[3];
    const float* bb1  = (const float*)d_in[4];
    const float* bw2  = (const float*)d_in[5];
    const float* bb2  = (const float*)d_in[6];
    const float* bw3  = (const float*)d_in[7];
    const float* bb3  = (const float*)d_in[8];
    const float* tw1  = (const float*)d_in[9];
    const float* tb1  = (const float*)d_in[10];
    const float* tw2  = (const float*)d_in[11];
    const float* tb2  = (const float*)d_in[12];
    const float* tw3  = (const float*)d_in[13];
    const float* tb3  = (const float*)d_in[14];
    const float* tw4  = (const float*)d_in[15];
    const float* tb4  = (const float*)d_in[16];
    const float* tw5  = (const float*)d_in[17];
    const float* tb5  = (const float*)d_in[18];
    float* out = (float*)d_out;

    float* h1  = sym_addr(g_h1);
    float* h2  = sym_addr(g_h2);
    float* bot = sym_addr(g_bot);
    float* x   = sym_addr(g_x);
    float* t1  = sym_addr(g_t1);
    float* t2  = sym_addr(g_t2);
    float* t3  = sym_addr(g_t3);
    float* t4  = sym_addr(g_t4);

    // bottom MLP
    bottom1_kernel<<<BATCH / 32, 256>>>(Xnum, bw1, bb1);
    gemm_bias_relu<<<dim3(256 / 128, BATCH / 128), 256>>>(h1, bw2, bb2, h2, 512, 256, 1);
    gemm_bias_relu<<<dim3(128 / 128, BATCH / 128), 256>>>(h2, bw3, bb3, bot, 256, 128, 1);

    // gather + pairwise interactions -> x[B, 480]
    interact_kernel<<<BATCH, 128>>>(cat, emb);

    // top MLP
    gemm_bias_relu<<<dim3(1024 / 128, BATCH / 128), 256>>>(x,  tw1, tb1, t1, TOPIN, 1024, 1);
    gemm_bias_relu<<<dim3(1024 / 128, BATCH / 128), 256>>>(t1, tw2, tb2, t2, 1024, 1024, 1);
    gemm_bias_relu<<<dim3(512  / 128, BATCH / 128), 256>>>(t2, tw3, tb3, t3, 1024, 512, 1);
    gemm_bias_relu<<<dim3(256  / 128, BATCH / 128), 256>>>(t3, tw4, tb4, t4, 512, 256, 1);

    // final dot + sigmoid
    final_kernel<<<BATCH / 8, 256>>>(tw5, tb5, out);
}

// round 3
// speedup vs baseline: 1.8567x; 1.8567x over previous
#include <cuda_runtime.h>
#include <cuda_bf16.h>
#include <cstdint>
#include <math.h>

#define BATCH   16384
#define EMB     128
#define NCAT    26
#define NPAIR   351
#define XDIM    512      /* 480 padded to 512 */

// ---------------- scratch (device globals; allocation-free) ----------------
__device__ float g_h1[BATCH * 512];
__device__ float g_h2[BATCH * 256];
__device__ float g_bot[BATCH * 128];
__device__ float g_x [BATCH * XDIM];
__device__ float g_t1[BATCH * 1024];
__device__ float g_t2[BATCH * 1024];
__device__ float g_t3[BATCH * 512];
__device__ float g_t4[BATCH * 256];
__device__ float g_w1p[1024 * XDIM];   // tw1 padded 480 -> 512

// ======================= helpers ============================================
__device__ __forceinline__ uint32_t smem_u32(const void* p) {
    uint32_t a;
    asm("{ .reg .u64 t; cvta.to.shared.u64 t, %1; cvt.u32.u64 %0, t; }"
        : "=r"(a) : "l"(p));
    return a;
}

__device__ __forceinline__ void split2(float a, float b, uint32_t& hi, uint32_t& lo) {
    __nv_bfloat162 h = __floats2bfloat162_rn(a, b);
    float ha = __bfloat162float(h.x), hb = __bfloat162float(h.y);
    __nv_bfloat162 l = __floats2bfloat162_rn(a - ha, b - hb);
    hi = *reinterpret_cast<uint32_t*>(&h);
    lo = *reinterpret_cast<uint32_t*>(&l);
}

#define LDSM4(r0, r1, r2, r3, addr) \
    asm volatile("ldmatrix.sync.aligned.m8n8.x4.shared.b16 {%0,%1,%2,%3}, [%4];" \
        : "=r"(r0), "=r"(r1), "=r"(r2), "=r"(r3) : "r"(addr))

#define MMA_BF16(c, a, b0, b1) \
    asm volatile("mma.sync.aligned.m16n8k16.row.col.f32.bf16.bf16.f32 " \
        "{%0,%1,%2,%3}, {%4,%5,%6,%7}, {%8,%9}, {%0,%1,%2,%3};" \
        : "+f"((c)[0]), "+f"((c)[1]), "+f"((c)[2]), "+f"((c)[3]) \
        : "r"((a)[0]), "r"((a)[1]), "r"((a)[2]), "r"((a)[3]), "r"(b0), "r"(b1))

// ============ tensor-core GEMM: C[M,N] = relu(A[M,K] @ W[N,K]^T + b) ========
// 128x128 CTA tile, 256 threads (8 warps, 2x4 grid of 64x32 warp tiles).
// K chunked by 16, double-buffered bf16 hi/lo smem, fp32 accumulators.
// smem layout per buffer: 4 arrays (Ahi,Alo,Whi,Wlo), each = 32 contiguous
// 8x8 bf16 matrices (128B each), mat index = (row/8)*2 + (k/8).
__global__ __launch_bounds__(256, 1) void gemm_tc(
    const float* __restrict__ A, const float* __restrict__ W,
    const float* __restrict__ bias, float* __restrict__ C,
    int K, int N, int relu)
{
    __shared__ __align__(16) unsigned char sbuf[2][4][4096];
    __shared__ float sbias[128];

    const int tid    = threadIdx.x;
    const int lane   = tid & 31;
    const int w      = tid >> 5;
    const int warp_m = w >> 2;        // 0..1
    const int warp_n = w & 3;         // 0..3
    const int row0   = blockIdx.y * 128;
    const int col0   = blockIdx.x * 128;

    if (tid < 128) sbias[tid] = bias[col0 + tid];

    const float* Ab = A + (size_t)row0 * K;
    const float* Wb = W + (size_t)col0 * K;

    // per-thread staging: 2 float4 of A, 2 float4 of W per chunk
    const int srow = tid >> 2;              // 0..63 (base row), +64 for i=1
    const int sc4  = (tid & 3) * 4;         // k offset within chunk
    // smem store target (same for both rows' pattern)
    const uint32_t st_off0 = (uint32_t)(((srow       >> 3) * 2 + (sc4 >> 3)) * 128
                                        + (srow  & 7) * 16 + (sc4 & 7) * 2);
    const uint32_t st_off1 = (uint32_t)(((((srow+64) >> 3) * 2 + (sc4 >> 3)) * 128
                                        + (srow  & 7) * 16 + (sc4 & 7) * 2));

    // ldmatrix lane offsets
    const int g  = lane >> 3;
    const int lr = lane & 7;
    const uint32_t laneA = (uint32_t)((g & 1) * 256 + (g >> 1) * 128 + lr * 16);
    const uint32_t laneB = (uint32_t)((g >> 1) * 256 + (g & 1) * 128 + lr * 16);
    const uint32_t sb0 = smem_u32(sbuf);

    float acc[4][4][4];
    #pragma unroll
    for (int i = 0; i < 4; i++)
        #pragma unroll
        for (int j = 0; j < 4; j++)
            #pragma unroll
            for (int e = 0; e < 4; e++) acc[i][j][e] = 0.0f;

    const int nk = K >> 4;
    float4 rA0, rA1, rW0, rW1;

    // prologue: load chunk 0, convert into buf 0
    rA0 = *(const float4*)(Ab + (size_t)srow        * K + sc4);
    rA1 = *(const float4*)(Ab + (size_t)(srow + 64) * K + sc4);
    rW0 = *(const float4*)(Wb + (size_t)srow        * K + sc4);
    rW1 = *(const float4*)(Wb + (size_t)(srow + 64) * K + sc4);
    {
        uint32_t h0, l0, h1, l1;
        unsigned char* bb = &sbuf[0][0][0];
        split2(rA0.x, rA0.y, h0, l0); split2(rA0.z, rA0.w, h1, l1);
        *(uint2*)(bb + st_off0)        = make_uint2(h0, h1);
        *(uint2*)(bb + 4096 + st_off0) = make_uint2(l0, l1);
        split2(rA1.x, rA1.y, h0, l0); split2(rA1.z, rA1.w, h1, l1);
        *(uint2*)(bb + st_off1)        = make_uint2(h0, h1);
        *(uint2*)(bb + 4096 + st_off1) = make_uint2(l0, l1);
        split2(rW0.x, rW0.y, h0, l0); split2(rW0.z, rW0.w, h1, l1);
        *(uint2*)(bb + 8192  + st_off0) = make_uint2(h0, h1);
        *(uint2*)(bb + 12288 + st_off0) = make_uint2(l0, l1);
        split2(rW1.x, rW1.y, h0, l0); split2(rW1.z, rW1.w, h1, l1);
        *(uint2*)(bb + 8192  + st_off1) = make_uint2(h0, h1);
        *(uint2*)(bb + 12288 + st_off1) = make_uint2(l0, l1);
    }
    __syncthreads();

    for (int ck = 0; ck < nk; ck++) {
        const int buf = ck & 1;
        const uint32_t bufb = sb0 + (uint32_t)buf * 16384;

        // issue loads for next chunk (non-blocking until consumed)
        if (ck + 1 < nk) {
            const int ko = (ck + 1) << 4;
            rA0 = *(const float4*)(Ab + (size_t)srow        * K + ko + sc4);
            rA1 = *(const float4*)(Ab + (size_t)(srow + 64) * K + ko + sc4);
            rW0 = *(const float4*)(Wb + (size_t)srow        * K + ko + sc4);
            rW1 = *(const float4*)(Wb + (size_t)(srow + 64) * K + ko + sc4);
        }

        // ---- MMA on current buffer ----
        uint32_t ah[4][4], al[4][4], bh[4][2], bl[4][2];
        #pragma unroll
        for (int mt = 0; mt < 4; mt++) {
            const uint32_t ta = bufb + (uint32_t)((warp_m * 8 + mt * 2) * 256) + laneA;
            LDSM4(ah[mt][0], ah[mt][1], ah[mt][2], ah[mt][3], ta);
            LDSM4(al[mt][0], al[mt][1], al[mt][2], al[mt][3], ta + 4096);
        }
        #pragma unroll
        for (int np = 0; np < 2; np++) {
            const uint32_t tb = bufb + 8192 + (uint32_t)((warp_n * 4 + np * 2) * 256) + laneB;
            uint32_t r0, r1, r2, r3;
            LDSM4(r0, r1, r2, r3, tb);
            bh[np*2][0] = r0; bh[np*2][1] = r1; bh[np*2+1][0] = r2; bh[np*2+1][1] = r3;
            LDSM4(r0, r1, r2, r3, tb + 4096);
            bl[np*2][0] = r0; bl[np*2][1] = r1; bl[np*2+1][0] = r2; bl[np*2+1][1] = r3;
        }
        #pragma unroll
        for (int mt = 0; mt < 4; mt++)
            #pragma unroll
            for (int nt = 0; nt < 4; nt++) {
                MMA_BF16(acc[mt][nt], ah[mt], bh[nt][0], bh[nt][1]);
                MMA_BF16(acc[mt][nt], ah[mt], bl[nt][0], bl[nt][1]);
                MMA_BF16(acc[mt][nt], al[mt], bh[nt][0], bh[nt][1]);
            }

        __syncthreads();

        // ---- convert staged regs into other buffer ----
        if (ck + 1 < nk) {
            uint32_t h0, l0, h1, l1;
            unsigned char* bb = &sbuf[buf ^ 1][0][0];
            split2(rA0.x, rA0.y, h0, l0); split2(rA0.z, rA0.w, h1, l1);
            *(uint2*)(bb + st_off0)        = make_uint2(h0, h1);
            *(uint2*)(bb + 4096 + st_off0) = make_uint2(l0, l1);
            split2(rA1.x, rA1.y, h0, l0); split2(rA1.z, rA1.w, h1, l1);
            *(uint2*)(bb + st_off1)        = make_uint2(h0, h1);
            *(uint2*)(bb + 4096 + st_off1) = make_uint2(l0, l1);
            split2(rW0.x, rW0.y, h0, l0); split2(rW0.z, rW0.w, h1, l1);
            *(uint2*)(bb + 8192  + st_off0) = make_uint2(h0, h1);
            *(uint2*)(bb + 12288 + st_off0) = make_uint2(l0, l1);
            split2(rW1.x, rW1.y, h0, l0); split2(rW1.z, rW1.w, h1, l1);
            *(uint2*)(bb + 8192  + st_off1) = make_uint2(h0, h1);
            *(uint2*)(bb + 12288 + st_off1) = make_uint2(l0, l1);
            __syncthreads();
        }
    }

    // ---- epilogue: bias + relu, direct float2 stores ----
    const int q  = lane >> 2;
    const int tq = lane & 3;
    #pragma unroll
    for (int mt = 0; mt < 4; mt++) {
        const int r0g = row0 + warp_m * 64 + mt * 16 + q;
        #pragma unroll
        for (int nt = 0; nt < 4; nt++) {
            const int cl = warp_n * 32 + nt * 8 + tq * 2;
            const float bx = sbias[cl], by = sbias[cl + 1];
            float v0 = acc[mt][nt][0] + bx, v1 = acc[mt][nt][1] + by;
            float v2 = acc[mt][nt][2] + bx, v3 = acc[mt][nt][3] + by;
            if (relu) {
                v0 = fmaxf(v0, 0.0f); v1 = fmaxf(v1, 0.0f);
                v2 = fmaxf(v2, 0.0f); v3 = fmaxf(v3, 0.0f);
            }
            *(float2*)(C + (size_t)r0g * N + col0 + cl)       = make_float2(v0, v1);
            *(float2*)(C + (size_t)(r0g + 8) * N + col0 + cl) = make_float2(v2, v3);
        }
    }
}

// ---------------- bottom layer 1: [B,13] -> [B,512], relu ------------------
__global__ __launch_bounds__(256) void bottom1_kernel(
    const float* __restrict__ X, const float* __restrict__ W,
    const float* __restrict__ bias)
{
    __shared__ float ws[512 * 13];
    __shared__ float bs[512];
    __shared__ float xs[32 * 13];
    const int tid  = threadIdx.x;
    const int row0 = blockIdx.x * 32;

    for (int i = tid; i < 512 * 13; i += 256) ws[i] = W[i];
    for (int i = tid; i < 512;      i += 256) bs[i] = bias[i];
    for (int i = tid; i < 32 * 13;  i += 256) xs[i] = X[row0 * 13 + i];
    __syncthreads();

    for (int o = tid; o < 32 * 512; o += 256) {
        const int col = o & 511;
        const int row = o >> 9;
        float acc = bs[col];
        #pragma unroll
        for (int k = 0; k < 13; k++)
            acc = fmaf(xs[row * 13 + k], ws[col * 13 + k], acc);
        g_h1[(row0 + row) * 512 + col] = fmaxf(acc, 0.0f);
    }
}

// ---------------- gather + pairwise interactions ---------------------------
// warp per sample, 4 samples per block. Features padded to 28 rows.
// smem: per sample 28 rows x 32 float4, XOR-swizzled:
//   unit(r, d4) = r*32 + (d4 ^ ((r>>2)&7))   -> conflict-free LDS.128
#define ISMEM (4 * 28 * 32 * 16)
__global__ __launch_bounds__(128) void interact_kernel(
    const int* __restrict__ cat, const float* __restrict__ emb)
{
    extern __shared__ float4 fsm[];
    const int warp = threadIdx.x >> 5;
    const int lane = threadIdx.x & 31;
    const int b    = blockIdx.x * 4 + warp;
    float4* F = fsm + warp * (28 * 32);

    // gather: row 0 = bottom, rows 1..26 = embeddings, row 27 = zeros
    F[lane] = ((const float4*)(g_bot + (size_t)b * EMB))[lane];
    #pragma unroll 1
    for (int t = 0; t < NCAT; t++) {
        const int idx = cat[t * BATCH + b];
        const int r = t + 1;
        F[r * 32 + (lane ^ ((r >> 2) & 7))] =
            ((const float4*)(emb + ((size_t)t * 100000 + idx) * EMB))[lane];
    }
    F[27 * 32 + (lane ^ 6)] = make_float4(0.f, 0.f, 0.f, 0.f);
    __syncwarp();

    float* xrow = g_x + (size_t)b * XDIM;

    // copy bottom to x[0:128]; zero x[479..511]
    ((float4*)xrow)[lane] = F[lane];
    if (lane == 0) xrow[479] = 0.0f;
    if (lane < 8) ((float4*)(xrow + 480))[lane] = make_float4(0.f, 0.f, 0.f, 0.f);

    if (lane < 28) {
        // lane -> (R, C) tile in the lower triangle of 7x7 tile grid
        int t = lane, R = 0;
        while (t >= R + 1) { t -= R + 1; R++; }
        const int C = t;
        const int sR = R & 7, sC = C & 7;

        float a[4][4];
        #pragma unroll
        for (int i = 0; i < 4; i++)
            #pragma unroll
            for (int j = 0; j < 4; j++) a[i][j] = 0.0f;

        #pragma unroll 4
        for (int d4 = 0; d4 < 32; d4++) {
            float4 fr[4], fc[4];
            #pragma unroll
            for (int i = 0; i < 4; i++)
                fr[i] = F[(4 * R + i) * 32 + (d4 ^ sR)];
            #pragma unroll
            for (int j = 0; j < 4; j++)
                fc[j] = F[(4 * C + j) * 32 + (d4 ^ sC)];
            #pragma unroll
            for (int i = 0; i < 4; i++)
                #pragma unroll
                for (int j = 0; j < 4; j++) {
                    a[i][j] = fmaf(fr[i].x, fc[j].x, a[i][j]);
                    a[i][j] = fmaf(fr[i].y, fc[j].y, a[i][j]);
                    a[i][j] = fmaf(fr[i].z, fc[j].z, a[i][j]);
                    a[i][j] = fmaf(fr[i].w, fc[j].w, a[i][j]);
                }
        }

        #pragma unroll
        for (int i = 0; i < 4; i++) {
            const int r = 4 * R + i;
            #pragma unroll
            for (int j = 0; j < 4; j++) {
                const int c = 4 * C + j;
                if (r < 27 && c < r)
                    xrow[EMB + r * (r - 1) / 2 + c] = a[i][j];
            }
        }
    }
}

// ---------------- pad tw1 [1024,480] -> [1024,512] --------------------------
__global__ __launch_bounds__(256) void pad_w1_kernel(const float* __restrict__ tw1)
{
    const int i = blockIdx.x * 256 + threadIdx.x;     // over 1024*512
    const int r = i >> 9, c = i & 511;
    g_w1p[i] = (c < 480) ? tw1[r * 480 + c] : 0.0f;
}

// ---------------- final layer: dot(256) + sigmoid ---------------------------
__global__ __launch_bounds__(256) void final_kernel(
    const float* __restrict__ w5, const float* __restrict__ b5,
    float* __restrict__ out)
{
    const int warp = threadIdx.x >> 5;
    const int lane = threadIdx.x & 31;
    const int b = blockIdx.x * 8 + warp;
    const float* row = g_t4 + (size_t)b * 256;
    float s = 0.0f;
    #pragma unroll
    for (int j = lane; j < 256; j += 32) s = fmaf(row[j], w5[j], s);
    #pragma unroll
    for (int o = 16; o; o >>= 1) s += __shfl_xor_sync(0xffffffffu, s, o);
    if (lane == 0) out[b] = 1.0f / (1.0f + expf(-(s + b5[0])));
}

// ---------------- launcher --------------------------------------------------
static float* sym_addr(const void* symbol)
{
    void* p = nullptr;
    cudaGetSymbolAddress(&p, symbol);
    return (float*)p;
}

extern "C" void kernel_launch(void* const* d_in, const int* in_sizes, int n_in,
                              void* d_out, int out_size)
{
    const float* Xnum = (const float*)d_in[0];
    const int*   cat  = (const int*)  d_in[1];
    const float* emb  = (const float*)d_in[2];
    const float* bw1  = (const float*)d_in[3];
    const float* bb1  = (const float*)d_in[4];
    const float* bw2  = (const float*)d_in[5];
    const float* bb2  = (const float*)d_in[6];
    const float* bw3  = (const float*)d_in[7];
    const float* bb3  = (const float*)d_in[8];
    const float* tw1  = (const float*)d_in[9];
    const float* tb1  = (const float*)d_in[10];
    const float* tw2  = (const float*)d_in[11];
    const float* tb2  = (const float*)d_in[12];
    const float* tw3  = (const float*)d_in[13];
    const float* tb3  = (const float*)d_in[14];
    const float* tw4  = (const float*)d_in[15];
    const float* tb4  = (const float*)d_in[16];
    const float* tw5  = (const float*)d_in[17];
    const float* tb5  = (const float*)d_in[18];
    float* out = (float*)d_out;

    float* h1  = sym_addr(g_h1);
    float* h2  = sym_addr(g_h2);
    float* bot = sym_addr(g_bot);
    float* x   = sym_addr(g_x);
    float* t1  = sym_addr(g_t1);
    float* t2  = sym_addr(g_t2);
    float* t3  = sym_addr(g_t3);
    float* t4  = sym_addr(g_t4);
    float* w1p = sym_addr(g_w1p);

    static int init_done = 0;
    if (!init_done) {
        cudaFuncSetAttribute(interact_kernel,
                             cudaFuncAttributeMaxDynamicSharedMemorySize, ISMEM);
        init_done = 1;
    }

    // bottom MLP
    bottom1_kernel<<<BATCH / 32, 256>>>(Xnum, bw1, bb1);
    gemm_tc<<<dim3(2, BATCH / 128), 256>>>(h1, bw2, bb2, h2, 512, 256, 1);
    gemm_tc<<<dim3(1, BATCH / 128), 256>>>(h2, bw3, bb3, bot, 256, 128, 1);

    // gather + interactions (writes g_x padded to 512); pad tw1
    interact_kernel<<<BATCH / 4, 128, ISMEM>>>(cat, emb);
    pad_w1_kernel<<<(1024 * 512) / 256, 256>>>(tw1);

    // top MLP
    gemm_tc<<<dim3(8, BATCH / 128), 256>>>(x,  w1p, tb1, t1, 512, 1024, 1);
    gemm_tc<<<dim3(8, BATCH / 128), 256>>>(t1, tw2, tb2, t2, 1024, 1024, 1);
    gemm_tc<<<dim3(4, BATCH / 128), 256>>>(t2, tw3, tb3, t3, 1024, 512, 1);
    gemm_tc<<<dim3(2, BATCH / 128), 256>>>(t3, tw4, tb4, t4, 512, 256, 1);

    // final dot + sigmoid
    final_kernel<<<BATCH / 8, 256>>>(tw5, tb5, out);
}